// round 14
// baseline (speedup 1.0000x reference)
#include <cuda_runtime.h>
#include <cuda_bf16.h>
#include <math.h>
#include <stdint.h>

#define B_   256
#define V_   50
#define D_   128
#define H_   384
#define L_   12
#define CS_  10
#define G_   1560
#define ND_  4096
#define HS_  64
#define OUT_ 128
#define KWP  (ND_ + 1)
#define RWP  (H_ + 1)
#define CK_  (H_ * CS_)   // 3840
#define KP   72           // smem row pitch (conflict-free ldmatrix)
#define NEMB 10001
#define NBLK 96           // scan grid: 24 gb x 4 rb
#define NSPL 20           // out-gemm split-K

// ---------------- device scratch ----------------
__device__ float g_XO2[(size_t)V_ * 24 * B_ * 96];   // [t][gb][row][96]
__device__ float g_c[B_ * H_];
__device__ __nv_bfloat16 g_hh[B_ * H_], g_hl[B_ * H_];
__device__ float g_hsf[(size_t)V_ * B_ * H_];     // [t][b][h]
__device__ float g_ld[B_ * V_ * CS_];             // [r=b*V+t][k]
__device__ float g_mean[(size_t)B_ * V_ * H_];
__device__ float g_relu[B_ * V_ * HS_];
__device__ float g_theme[(size_t)B_ * V_ * H_];
__device__ float g_rnn[(size_t)B_ * V_ * H_];     // [b][t][h]
__device__ float g_opart[NSPL * B_ * OUT_];
// pre-converted split-bf16 weights / embed
__device__ __nv_bfloat16 g_kwh[(size_t)G_ * ND_], g_kwl[(size_t)G_ * ND_];
__device__ __nv_bfloat16 g_rwh[G_ * H_], g_rwl[G_ * H_];
__device__ __nv_bfloat16 g_cwh[H_ * CK_], g_cwl[H_ * CK_];
__device__ __nv_bfloat16 g_emh[NEMB * D_], g_eml[NEMB * D_];
__device__ float g_bias2[G_], g_lin2[G_];

// software grid barrier state
__device__ volatile unsigned g_gen;
__device__ unsigned g_cnt;

__device__ __forceinline__ float sigf(float x) { return 1.f / (1.f + expf(-x)); }
__device__ __forceinline__ void bf16_split(float a, __nv_bfloat16& h, __nv_bfloat16& l) {
    h = __float2bfloat16(a);
    l = __float2bfloat16(a - __bfloat162float(h));
}

// ---------------- async copy helpers ----------------
__device__ __forceinline__ void cpa16(void* dst, const void* src) {
    uint32_t d = (uint32_t)__cvta_generic_to_shared(dst);
    asm volatile("cp.async.cg.shared.global [%0], [%1], 16;" :: "r"(d), "l"(src));
}
__device__ __forceinline__ void cpa_commit() { asm volatile("cp.async.commit_group;"); }
template<int N> __device__ __forceinline__ void cpa_wait() {
    asm volatile("cp.async.wait_group %0;" :: "n"(N));
}

// ---------------- mma helpers ----------------
__device__ __forceinline__ void ldsm4(uint32_t* r, const void* p) {
    uint32_t a = (uint32_t)__cvta_generic_to_shared(p);
    asm volatile("ldmatrix.sync.aligned.m8n8.x4.shared.b16 {%0,%1,%2,%3},[%4];"
                 : "=r"(r[0]), "=r"(r[1]), "=r"(r[2]), "=r"(r[3]) : "r"(a));
}
__device__ __forceinline__ void mma16816(float* c, const uint32_t* a, const uint32_t* b) {
    asm volatile("mma.sync.aligned.m16n8k16.row.col.f32.bf16.bf16.f32 "
                 "{%0,%1,%2,%3},{%4,%5,%6,%7},{%8,%9},{%0,%1,%2,%3};"
                 : "+f"(c[0]), "+f"(c[1]), "+f"(c[2]), "+f"(c[3])
                 : "r"(a[0]), "r"(a[1]), "r"(a[2]), "r"(a[3]), "r"(b[0]), "r"(b[1]));
}

// ---------------- prep: convert weights/embed, zero state ----------------
__global__ void k_prep(const float* __restrict__ kw, const float* __restrict__ rw,
                       const float* __restrict__ cw, const float* __restrict__ embed,
                       const float* __restrict__ kb, const float* __restrict__ rb_)
{
    int64_t i0 = (int64_t)blockIdx.x * blockDim.x + threadIdx.x;
    int64_t stride = (int64_t)gridDim.x * blockDim.x;
    for (int64_t i = i0; i < (int64_t)G_ * ND_; i += stride) {
        int g = (int)(i >> 12), k = (int)(i & (ND_ - 1));
        __nv_bfloat16 h, l;
        bf16_split(kw[(size_t)g * KWP + k], h, l);
        g_kwh[i] = h; g_kwl[i] = l;
    }
    for (int64_t i = i0; i < (int64_t)G_ * H_; i += stride) {
        int g = (int)(i / H_), k = (int)(i % H_);
        __nv_bfloat16 h, l;
        bf16_split(rw[(size_t)g * RWP + k], h, l);
        g_rwh[i] = h; g_rwl[i] = l;
    }
    for (int64_t i = i0; i < (int64_t)H_ * CK_; i += stride) {
        int o = (int)(i / CK_), rem = (int)(i % CK_);
        int k = rem / H_, hh = rem % H_;
        __nv_bfloat16 h, l;
        bf16_split(cw[((size_t)o * H_ + hh) * CS_ + k], h, l);
        g_cwh[i] = h; g_cwl[i] = l;
    }
    for (int64_t i = i0; i < (int64_t)NEMB * D_; i += stride) {
        __nv_bfloat16 h, l;
        bf16_split(embed[i], h, l);
        g_emh[i] = h; g_eml[i] = l;
    }
    for (int64_t i = i0; i < G_; i += stride) {
        g_bias2[i] = kb[i] + rb_[i];
        g_lin2[i]  = kw[(size_t)i * KWP + ND_] + rw[(size_t)i * RWP + H_];
    }
    __nv_bfloat16 zb = __float2bfloat16(0.f);
    for (int64_t i = i0; i < B_ * H_; i += stride) { g_c[i] = 0.f; g_hh[i] = zb; g_hl[i] = zb; }
}

// ---------------- phase 1: XO2 = gather(embed) @ kernel_w.T + bias2 + tv*lin2 ----
// 128x64 block tile, 8 warps of 32x32, cp.async 2-stage pipeline.
// stage s layout (55296 B each): Ah(18432) Al(18432) Bh(9216) Bl(9216); ids at 110592.
__global__ void __launch_bounds__(256) k_pre_gemm(
    const int* __restrict__ node_ids, const float* __restrict__ tim)
{
    extern __shared__ char smp[];
    int (*ids)[32] = (int (*)[32])(smp + 110592);

    const int tid = threadIdx.x, lane = tid & 31, wid = tid >> 5;
    const int r0 = blockIdx.x * 128, g0 = blockIdx.y * 64;
    const int m0w = (wid & 3) * 32, n0w = (wid >> 2) * 32;
    float acc[2][4][4];
#pragma unroll
    for (int mt = 0; mt < 2; mt++)
#pragma unroll
        for (int nt = 0; nt < 4; nt++)
#pragma unroll
            for (int e = 0; e < 4; e++) acc[mt][nt][e] = 0.f;

    for (int idx = tid; idx < 128 * 32; idx += 256) {
        int row = idx >> 5, c = idx & 31;
        int r = r0 + row;
        ids[row][c] = node_ids[((r & 255) * V_ + (r >> 8)) * 32 + c];
    }

    const int lrA = tid >> 1, lkA = (tid & 1) * 32;
    const int lrB = tid >> 2, lkB = (tid & 3) * 16;

    // zero-fill dead B rows once, both stages
    if (g0 + lrB >= G_) {
        uint4 z = {0, 0, 0, 0};
#pragma unroll
        for (int s = 0; s < 2; s++) {
            __nv_bfloat16 (*Bh)[KP] = (__nv_bfloat16 (*)[KP])(smp + s * 55296 + 36864);
            __nv_bfloat16 (*Bl)[KP] = (__nv_bfloat16 (*)[KP])(smp + s * 55296 + 46080);
            *(uint4*)&Bh[lrB][lkB] = z; *(uint4*)&Bh[lrB][lkB + 8] = z;
            *(uint4*)&Bl[lrB][lkB] = z; *(uint4*)&Bl[lrB][lkB + 8] = z;
        }
    }
    __syncthreads();

    // issue loader for chunk c into stage s
    auto loadChunk = [&](int c, int s) {
        char* sb = smp + s * 55296;
        __nv_bfloat16 (*Ah)[KP] = (__nv_bfloat16 (*)[KP])(sb);
        __nv_bfloat16 (*Al)[KP] = (__nv_bfloat16 (*)[KP])(sb + 18432);
        __nv_bfloat16 (*Bh)[KP] = (__nv_bfloat16 (*)[KP])(sb + 36864);
        __nv_bfloat16 (*Bl)[KP] = (__nv_bfloat16 (*)[KP])(sb + 46080);
        const int k0 = c * 64;
        size_t base = (size_t)ids[lrA][k0 >> 7] * D_ + (k0 & 127) + lkA;
#pragma unroll
        for (int q = 0; q < 32; q += 8) {
            cpa16(&Ah[lrA][lkA + q], g_emh + base + q);
            cpa16(&Al[lrA][lkA + q], g_eml + base + q);
        }
        int g = g0 + lrB;
        if (g < G_) {
            size_t b2 = (size_t)g * ND_ + k0 + lkB;
            cpa16(&Bh[lrB][lkB],     g_kwh + b2);
            cpa16(&Bh[lrB][lkB + 8], g_kwh + b2 + 8);
            cpa16(&Bl[lrB][lkB],     g_kwl + b2);
            cpa16(&Bl[lrB][lkB + 8], g_kwl + b2 + 8);
        }
    };

    loadChunk(0, 0);
    cpa_commit();

    for (int c = 0; c < 64; c++) {
        if (c < 63) { loadChunk(c + 1, (c + 1) & 1); cpa_commit(); }
        if (c < 63) cpa_wait<1>(); else cpa_wait<0>();
        __syncthreads();
        char* sb = smp + (c & 1) * 55296;
        __nv_bfloat16 (*Ah)[KP] = (__nv_bfloat16 (*)[KP])(sb);
        __nv_bfloat16 (*Al)[KP] = (__nv_bfloat16 (*)[KP])(sb + 18432);
        __nv_bfloat16 (*Bh)[KP] = (__nv_bfloat16 (*)[KP])(sb + 36864);
        __nv_bfloat16 (*Bl)[KP] = (__nv_bfloat16 (*)[KP])(sb + 46080);
#pragma unroll
        for (int kh = 0; kh < 64; kh += 16) {
            uint32_t ah[2][4], al[2][4], bh[4][2], bl[4][2], t4[4];
            const int ar = lane & 15, ac = kh + (lane >> 4) * 8;
#pragma unroll
            for (int mt = 0; mt < 2; mt++) {
                ldsm4(ah[mt], &Ah[m0w + mt * 16 + ar][ac]);
                ldsm4(al[mt], &Al[m0w + mt * 16 + ar][ac]);
            }
            const int brow = ((lane >> 4) << 3) + (lane & 7);
            const int bcol = kh + ((lane >> 3) & 1) * 8;
#pragma unroll
            for (int p = 0; p < 2; p++) {
                ldsm4(t4, &Bh[n0w + p * 16 + brow][bcol]);
                bh[p * 2][0] = t4[0]; bh[p * 2][1] = t4[1];
                bh[p * 2 + 1][0] = t4[2]; bh[p * 2 + 1][1] = t4[3];
                ldsm4(t4, &Bl[n0w + p * 16 + brow][bcol]);
                bl[p * 2][0] = t4[0]; bl[p * 2][1] = t4[1];
                bl[p * 2 + 1][0] = t4[2]; bl[p * 2 + 1][1] = t4[3];
            }
#pragma unroll
            for (int mt = 0; mt < 2; mt++)
#pragma unroll
                for (int nt = 0; nt < 4; nt++) {
                    mma16816(acc[mt][nt], ah[mt], bh[nt]);
                    mma16816(acc[mt][nt], ah[mt], bl[nt]);
                    mma16816(acc[mt][nt], al[mt], bh[nt]);
                }
        }
        __syncthreads();
    }

    // epilogue: scatter into XO2 [t][gb][row(b)][96]
#pragma unroll
    for (int mt = 0; mt < 2; mt++)
#pragma unroll
        for (int half = 0; half < 2; half++) {
            int row = r0 + m0w + mt * 16 + (lane >> 2) + half * 8;
            int b = row & 255, v = row >> 8;
            float tv = tim[b * V_ + v];
#pragma unroll
            for (int nt = 0; nt < 4; nt++)
#pragma unroll
                for (int e = 0; e < 2; e++) {
                    int g = g0 + n0w + nt * 8 + (lane & 3) * 2 + e;
                    if (g < G_) {
                        float val = acc[mt][nt][half * 2 + e] + g_bias2[g] + tv * g_lin2[g];
                        if (g < 24) {
                            for (int gb2 = 0; gb2 < 24; gb2++)
                                g_XO2[((size_t)(v * 24 + gb2) * B_ + b) * 96 + g] = val;
                        } else {
                            int q = g - 24;
                            int seg = q / 384;
                            int hl = q - seg * 384;
                            int gb = hl >> 4;
                            int j = 24 + seg * 16 + (hl & 15);
                            g_XO2[((size_t)(v * 24 + gb) * B_ + b) * 96 + j] = val;
                        }
                    }
                }
        }
}

// ---------------- fused persistent scan ----------------
__device__ __forceinline__ void gbar() {
    __syncthreads();
    if (threadIdx.x == 0) {
        unsigned g = g_gen;
        __threadfence();
        if (atomicAdd(&g_cnt, 1u) == NBLK - 1u) {
            g_cnt = 0;
            __threadfence();
            g_gen = g + 1u;
        } else {
            while (g_gen == g) { }
        }
        __threadfence();
    }
    __syncthreads();
}

__device__ __forceinline__ int scan_gcol(int j, int gb) {
    if (j < 24) return j;
    int q = j - 24, seg = q >> 4, hl = q & 15;
    return 24 + seg * 384 + 16 * gb + hl;
}

// smem: BH 0..82944, BL ..165888, A stages (2x18432) ..202752,
//       s_xo (64x100 f32) ..228352, fmv 228352, imv 228608  => 228864
__global__ void __launch_bounds__(256) k_scan(float* __restrict__ dists)
{
    extern __shared__ char sm[];
    __nv_bfloat16* BHall = (__nv_bfloat16*)(sm);
    __nv_bfloat16* BLall = (__nv_bfloat16*)(sm + 82944);
    float (*s_xo)[100]   = (float (*)[100])(sm + 202752);
    float* s_fmv         = (float*)(sm + 228352);
    float* s_imv         = (float*)(sm + 228608);

    const int tid = threadIdx.x, lane = tid & 31, wid = tid >> 5;
    const int gb = blockIdx.x, rb = blockIdx.y;
    const int m0 = (wid & 3) * 16;
    const int n0 = (wid >> 2) * 48;
    const int lfm = gb >> 1;

    // preload resident B: rec_w tile for this gb
    for (int idx = tid; idx < 6 * 96 * 8; idx += 256) {
        int c = idx / 768, rem = idx - c * 768;
        int j = rem >> 3, q = (rem & 7) * 8;
        __nv_bfloat16* dh = BHall + (size_t)(c * 96 + j) * KP + q;
        __nv_bfloat16* dl = BLall + (size_t)(c * 96 + j) * KP + q;
        if (j < 88) {
            int g = scan_gcol(j, gb);
            size_t base = (size_t)g * H_ + c * 64 + q;
            *(uint4*)dh = *(const uint4*)(g_rwh + base);
            *(uint4*)dl = *(const uint4*)(g_rwl + base);
        } else {
            uint4 z = {0, 0, 0, 0};
            *(uint4*)dh = z; *(uint4*)dl = z;
        }
    }
    __syncthreads();

    const int rA = tid >> 2, qA = (tid & 3) * 16;

    auto loadA = [&](int c, int s) {
        char* sb = sm + 165888 + s * 18432;
        __nv_bfloat16 (*AhS)[KP] = (__nv_bfloat16 (*)[KP])(sb);
        __nv_bfloat16 (*AlS)[KP] = (__nv_bfloat16 (*)[KP])(sb + 9216);
        size_t base = (size_t)(rb * 64 + rA) * H_ + c * 64 + qA;
        cpa16(&AhS[rA][qA],     g_hh + base);
        cpa16(&AhS[rA][qA + 8], g_hh + base + 8);
        cpa16(&AlS[rA][qA],     g_hl + base);
        cpa16(&AlS[rA][qA + 8], g_hl + base + 8);
    };

    for (int t = 0; t < V_; t++) {
        float acc[6][4];
#pragma unroll
        for (int nf = 0; nf < 6; nf++)
#pragma unroll
            for (int e = 0; e < 4; e++) acc[nf][e] = 0.f;

        // prefetch XO2 tile into s_xo + first A chunk (one group)
        {
            const float* xob = g_XO2 + ((size_t)(t * 24 + gb) * B_ + rb * 64) * 96;
            for (int idx = tid; idx < 64 * 22; idx += 256) {
                int r = idx / 22, qq = idx - r * 22;
                cpa16((char*)s_xo + r * 400 + qq * 16, xob + (size_t)r * 96 + qq * 4);
            }
            loadA(0, 0);
            cpa_commit();
        }

        for (int c = 0; c < 6; c++) {
            if (c < 5) { loadA(c + 1, (c + 1) & 1); cpa_commit(); }
            if (c < 5) cpa_wait<1>(); else cpa_wait<0>();
            __syncthreads();
            char* sb = sm + 165888 + (c & 1) * 18432;
            __nv_bfloat16 (*AhS)[KP] = (__nv_bfloat16 (*)[KP])(sb);
            __nv_bfloat16 (*AlS)[KP] = (__nv_bfloat16 (*)[KP])(sb + 9216);
#pragma unroll
            for (int kh = 0; kh < 64; kh += 16) {
                uint32_t ah[4], al[4], bh[6][2], bl[6][2], t4[4];
                const int ar = lane & 15, ac = kh + (lane >> 4) * 8;
                ldsm4(ah, &AhS[m0 + ar][ac]);
                ldsm4(al, &AlS[m0 + ar][ac]);
                const int brow = ((lane >> 4) << 3) + (lane & 7);
                const int bcol = kh + ((lane >> 3) & 1) * 8;
#pragma unroll
                for (int p = 0; p < 3; p++) {
                    const __nv_bfloat16* bp = BHall + (size_t)(c * 96 + n0 + p * 16 + brow) * KP + bcol;
                    ldsm4(t4, bp);
                    bh[p * 2][0] = t4[0]; bh[p * 2][1] = t4[1];
                    bh[p * 2 + 1][0] = t4[2]; bh[p * 2 + 1][1] = t4[3];
                    const __nv_bfloat16* bq = BLall + (size_t)(c * 96 + n0 + p * 16 + brow) * KP + bcol;
                    ldsm4(t4, bq);
                    bl[p * 2][0] = t4[0]; bl[p * 2][1] = t4[1];
                    bl[p * 2 + 1][0] = t4[2]; bl[p * 2 + 1][1] = t4[3];
                }
#pragma unroll
                for (int nf = 0; nf < 6; nf++) {
                    mma16816(acc[nf], ah, bh[nf]);
                    mma16816(acc[nf], ah, bl[nf]);
                    mma16816(acc[nf], al, bh[nf]);
                }
            }
            __syncthreads();
        }

        // epilogue: s_xo (holds XO2) += acc
        {
            const int rloc0 = m0 + (lane >> 2);
#pragma unroll
            for (int half = 0; half < 2; half++) {
                int rloc = rloc0 + half * 8;
#pragma unroll
                for (int nf = 0; nf < 6; nf++) {
                    int j = n0 + nf * 8 + (lane & 3) * 2;
                    if (j < 88) {
                        s_xo[rloc][j]     += acc[nf][half * 2];
                        s_xo[rloc][j + 1] += acc[nf][half * 2 + 1];
                    }
                }
            }
        }
        __syncthreads();

        // fm/im
        if (tid < 64) {
            const int r = tid;
            float a[L_], mx = -1e30f;
#pragma unroll
            for (int i = 0; i < L_; i++) { a[i] = s_xo[r][i]; mx = fmaxf(mx, a[i]); }
            float s = 0.f;
#pragma unroll
            for (int i = 0; i < L_; i++) { a[i] = expf(a[i] - mx); s += a[i]; }
            float inv = 1.f / s, cum = 0.f, fsum = 0.f, fmv = 0.f;
#pragma unroll
            for (int i = 0; i < L_; i++) {
                cum += a[i] * inv;
                if (i == lfm) fmv = cum;
                fsum += cum;
            }
            s_fmv[r] = fmv;
            if (gb == 0) dists[t * B_ + rb * 64 + r] = 1.f - fsum / (float)L_;
        } else if (tid < 128) {
            const int r = tid - 64;
            float a[L_], mx = -1e30f;
#pragma unroll
            for (int i = 0; i < L_; i++) { a[i] = s_xo[r][12 + i]; mx = fmaxf(mx, a[i]); }
            float s = 0.f;
#pragma unroll
            for (int i = 0; i < L_; i++) { a[i] = expf(a[i] - mx); s += a[i]; }
            float suf = 0.f, imv = 0.f;
#pragma unroll
            for (int i = L_ - 1; i >= 0; i--) {
                suf += a[i];
                if (i == lfm) imv = suf;
            }
            s_imv[r] = imv / s;
        }
        __syncthreads();

        // cell/h update: 64 rows x 16 h
#pragma unroll
        for (int q = tid; q < 1024; q += 256) {
            const int r = q >> 4, hloc = q & 15;
            const int b = rb * 64 + r, h = 16 * gb + hloc;
            float f  = sigf(s_xo[r][24 + hloc]);
            float i_ = sigf(s_xo[r][40 + hloc]);
            float o  = sigf(s_xo[r][56 + hloc]);
            float ci = tanhf(s_xo[r][72 + hloc]);
            float cc = g_c[b * H_ + h];
            float fm = s_fmv[r], im = s_imv[r], ov = fm * im;
            float cn = ov * (f * cc + i_ * ci) + (fm - ov) * cc + (im - ov) * ci;
            float hn = o * tanhf(cn);
            g_c[b * H_ + h] = cn;
            __nv_bfloat16 hh, hl; bf16_split(hn, hh, hl);
            g_hh[b * H_ + h] = hh; g_hl[b * H_ + h] = hl;
            g_hsf[((size_t)t * B_ + b) * H_ + h] = hn;
            g_rnn[((size_t)b * V_ + t) * H_ + h] = hn;
        }

        gbar();
    }
}

// ---------------- post: ld (warp-parallel) + mean over window ----------------
__global__ void __launch_bounds__(384) k_mean(const float* __restrict__ dists)
{
    const int r = blockIdx.x, tid = threadIdx.x;
    const int b = r / V_, t = r - b * V_;
    __shared__ float sld[16];
    if (tid < 32) {
        int lane = tid;
        int j = t - 9 + lane;
        float d = (lane < CS_ && j >= 0) ? dists[j * B_ + b] : 0.f;
        float c = d;
#pragma unroll
        for (int o = 1; o < 16; o <<= 1) {
            float n = __shfl_up_sync(0xFFFFFFFF, c, o);
            if (lane >= o) c += n;
        }
        float mx = (lane < CS_) ? c : -1e30f;
#pragma unroll
        for (int o = 16; o > 0; o >>= 1) mx = fmaxf(mx, __shfl_xor_sync(0xFFFFFFFF, mx, o));
        float e = (lane < CS_) ? expf(c - mx) : 0.f;
        float s = e;
#pragma unroll
        for (int o = 16; o > 0; o >>= 1) s += __shfl_xor_sync(0xFFFFFFFF, s, o);
        float v = e / s;
        if (lane < CS_) { sld[lane] = v; g_ld[r * CS_ + lane] = v; }
    }
    __syncthreads();
    const int j0 = (t - 9 < 0) ? 0 : t - 9;
    const float* p = g_hsf + ((size_t)j0 * B_ + b) * H_ + tid;
    float m = 0.f;
    for (int j = j0; j <= t; j++) {
        m += (*p) * sld[j - t + 9];
        p += (size_t)B_ * H_;
    }
    g_mean[(size_t)r * H_ + tid] = m * (1.f / (float)CS_);
}

// ---------------- post: relu(mean @ scale_w.T + b) ----------------
__global__ void __launch_bounds__(256) k_scale_gemm(
    const float* __restrict__ sw, const float* __restrict__ sb)
{
    __shared__ float As[32][65];
    __shared__ float Bs[32][65];
    const int tid = threadIdx.x;
    const int r0 = blockIdx.x * 64;
    const int ty = tid >> 4, tx = tid & 15;
    float acc[4][4] = {};
    const int lrb = tid >> 5, lkk = tid & 31;

    for (int k0 = 0; k0 < H_; k0 += 32) {
#pragma unroll
        for (int j = 0; j < 8; j++) {
            int r = lrb + 8 * j;
            As[lkk][r] = g_mean[(size_t)(r0 + r) * H_ + k0 + lkk];
            Bs[lkk][r] = (r < HS_) ? sw[r * H_ + k0 + lkk] : 0.f;
        }
        __syncthreads();
#pragma unroll
        for (int kk = 0; kk < 32; kk++) {
            float ra[4], rb[4];
#pragma unroll
            for (int m = 0; m < 4; m++) ra[m] = As[kk][ty * 4 + m];
#pragma unroll
            for (int n = 0; n < 4; n++) rb[n] = Bs[kk][tx * 4 + n];
#pragma unroll
            for (int m = 0; m < 4; m++)
#pragma unroll
                for (int n = 0; n < 4; n++) acc[m][n] += ra[m] * rb[n];
        }
        __syncthreads();
    }
#pragma unroll
    for (int m = 0; m < 4; m++) {
        int r = r0 + ty * 4 + m;
#pragma unroll
        for (int n = 0; n < 4; n++) {
            int s2 = tx * 4 + n;
            if (s2 < HS_) g_relu[r * HS_ + s2] = fmaxf(acc[m][n] + sb[s2], 0.f);
        }
    }
}

// ---------------- post: theme = sigmoid(relu @ rescale_w.T + b) ----------------
__global__ void __launch_bounds__(256) k_theme_gemm(
    const float* __restrict__ rsw, const float* __restrict__ rsb)
{
    __shared__ float As[32][65];
    __shared__ float Bs[32][65];
    const int tid = threadIdx.x;
    const int r0 = blockIdx.x * 64, o0 = blockIdx.y * 64;
    const int ty = tid >> 4, tx = tid & 15;
    float acc[4][4] = {};
    const int lrb = tid >> 5, lkk = tid & 31;

    for (int k0 = 0; k0 < HS_; k0 += 32) {
#pragma unroll
        for (int j = 0; j < 8; j++) {
            int r = lrb + 8 * j;
            As[lkk][r] = g_relu[(r0 + r) * HS_ + k0 + lkk];
            Bs[lkk][r] = rsw[(o0 + r) * HS_ + k0 + lkk];
        }
        __syncthreads();
#pragma unroll
        for (int kk = 0; kk < 32; kk++) {
            float ra[4], rb[4];
#pragma unroll
            for (int m = 0; m < 4; m++) ra[m] = As[kk][ty * 4 + m];
#pragma unroll
            for (int n = 0; n < 4; n++) rb[n] = Bs[kk][tx * 4 + n];
#pragma unroll
            for (int m = 0; m < 4; m++)
#pragma unroll
                for (int n = 0; n < 4; n++) acc[m][n] += ra[m] * rb[n];
        }
        __syncthreads();
    }
#pragma unroll
    for (int m = 0; m < 4; m++) {
        int r = r0 + ty * 4 + m;
#pragma unroll
        for (int n = 0; n < 4; n++) {
            int o = o0 + tx * 4 + n;
            g_theme[(size_t)r * H_ + o] = sigf(acc[m][n] + rsb[o]);
        }
    }
}

// ---------------- post: conv GEMM over ALL t, lh on the fly ----------------
__global__ void __launch_bounds__(256) k_conv_big(const float* __restrict__ cb)
{
    __shared__ __nv_bfloat16 Ah[64][KP], Al[64][KP], Bh[64][KP], Bl[64][KP];
    const int tid = threadIdx.x, lane = tid & 31, wid = tid >> 5;
    const int r0 = blockIdx.x * 64, o0 = blockIdx.y * 64;
    const int m0w = (wid & 1) * 32, n0w = (wid >> 1) * 16;
    float acc[2][2][4] = {};
    const int lr = tid >> 2, lk = (tid & 3) * 16;
    const int rr = r0 + lr, bb = rr / V_, tt = rr % V_;

    for (int k0 = 0; k0 < CK_; k0 += 64) {
        const int k = k0 / H_;
        const int hb = k0 % H_;
        const int j = tt - (CS_ - 1) + k;
        if (j >= 0) {
            const float ldv = g_ld[rr * CS_ + k];
            const float* hp = g_hsf + ((size_t)j * B_ + bb) * H_ + hb + lk;
#pragma unroll
            for (int q = 0; q < 4; q++) {
                float4 v = *(const float4*)(hp + q * 4);
                float va[4] = {v.x * ldv, v.y * ldv, v.z * ldv, v.w * ldv};
#pragma unroll
                for (int e = 0; e < 4; e++) {
                    __nv_bfloat16 h, l; bf16_split(va[e], h, l);
                    Ah[lr][lk + q * 4 + e] = h; Al[lr][lk + q * 4 + e] = l;
                }
            }
        } else {
            uint4 z = {0, 0, 0, 0};
            *(uint4*)&Ah[lr][lk] = z; *(uint4*)&Ah[lr][lk + 8] = z;
            *(uint4*)&Al[lr][lk] = z; *(uint4*)&Al[lr][lk + 8] = z;
        }
        *(uint4*)&Bh[lr][lk]     = *(const uint4*)(g_cwh + (size_t)(o0 + lr) * CK_ + k0 + lk);
        *(uint4*)&Bh[lr][lk + 8] = *(const uint4*)(g_cwh + (size_t)(o0 + lr) * CK_ + k0 + lk + 8);
        *(uint4*)&Bl[lr][lk]     = *(const uint4*)(g_cwl + (size_t)(o0 + lr) * CK_ + k0 + lk);
        *(uint4*)&Bl[lr][lk + 8] = *(const uint4*)(g_cwl + (size_t)(o0 + lr) * CK_ + k0 + lk + 8);
        __syncthreads();
#pragma unroll
        for (int kh = 0; kh < 64; kh += 16) {
            uint32_t ah[2][4], al[2][4], bh[2][2], bl[2][2], t4[4];
            const int ar = lane & 15, ac = kh + (lane >> 4) * 8;
#pragma unroll
            for (int mt = 0; mt < 2; mt++) {
                ldsm4(ah[mt], &Ah[m0w + mt * 16 + ar][ac]);
                ldsm4(al[mt], &Al[m0w + mt * 16 + ar][ac]);
            }
            const int brow = ((lane >> 4) << 3) + (lane & 7);
            const int bcol = kh + ((lane >> 3) & 1) * 8;
            ldsm4(t4, &Bh[n0w + brow][bcol]);
            bh[0][0] = t4[0]; bh[0][1] = t4[1]; bh[1][0] = t4[2]; bh[1][1] = t4[3];
            ldsm4(t4, &Bl[n0w + brow][bcol]);
            bl[0][0] = t4[0]; bl[0][1] = t4[1]; bl[1][0] = t4[2]; bl[1][1] = t4[3];
#pragma unroll
            for (int mt = 0; mt < 2; mt++)
#pragma unroll
                for (int nt = 0; nt < 2; nt++) {
                    mma16816(acc[mt][nt], ah[mt], bh[nt]);
                    mma16816(acc[mt][nt], ah[mt], bl[nt]);
                    mma16816(acc[mt][nt], al[mt], bh[nt]);
                }
        }
        __syncthreads();
    }

#pragma unroll
    for (int mt = 0; mt < 2; mt++)
#pragma unroll
        for (int half = 0; half < 2; half++) {
            int row = r0 + m0w + mt * 16 + (lane >> 2) + half * 8;
#pragma unroll
            for (int nt = 0; nt < 2; nt++)
#pragma unroll
                for (int e = 0; e < 2; e++) {
                    int o = o0 + n0w + nt * 8 + (lane & 3) * 2 + e;
                    float conv = acc[mt][nt][half * 2 + e] + cb[o];
                    g_rnn[(size_t)row * H_ + o] += g_theme[(size_t)row * H_ + o] * conv;
                }
        }
}

// ---------------- final out GEMM (fp32 SIMT, split-K 20) ----------------
__global__ void __launch_bounds__(256) k_out_gemm(const float* __restrict__ ow)
{
    __shared__ float As[32][65];
    __shared__ float Bs[32][65];
    const int tid = threadIdx.x;
    const int r0 = blockIdx.x * 64, o0 = blockIdx.y * 64;
    const int z = blockIdx.z, kbase = z * 960;
    const int ty = tid >> 4, tx = tid & 15;
    float acc[4][4] = {};
    const int lrb = tid >> 5, lkk = tid & 31;

    for (int k0 = 0; k0 < 960; k0 += 32) {
#pragma unroll
        for (int j = 0; j < 8; j++) {
            int r = lrb + 8 * j;
            As[lkk][r] = g_rnn[(size_t)(r0 + r) * (V_ * H_) + kbase + k0 + lkk];
            Bs[lkk][r] = ow[(size_t)(o0 + r) * (V_ * H_) + kbase + k0 + lkk];
        }
        __syncthreads();
#pragma unroll
        for (int kk = 0; kk < 32; kk++) {
            float ra[4], rb[4];
#pragma unroll
            for (int m = 0; m < 4; m++) ra[m] = As[kk][ty * 4 + m];
#pragma unroll
            for (int n = 0; n < 4; n++) rb[n] = Bs[kk][tx * 4 + n];
#pragma unroll
            for (int m = 0; m < 4; m++)
#pragma unroll
                for (int n = 0; n < 4; n++) acc[m][n] += ra[m] * rb[n];
        }
        __syncthreads();
    }
#pragma unroll
    for (int m = 0; m < 4; m++) {
        int r = r0 + ty * 4 + m;
#pragma unroll
        for (int n = 0; n < 4; n++) {
            int o = o0 + tx * 4 + n;
            g_opart[((size_t)z * B_ + r) * OUT_ + o] = acc[m][n];
        }
    }
}

__global__ void k_reduce_out(const float* __restrict__ ob, float* __restrict__ out)
{
    int idx = blockIdx.x * blockDim.x + threadIdx.x;
    if (idx < B_ * OUT_) {
        float s = ob[idx & (OUT_ - 1)];
#pragma unroll
        for (int z = 0; z < NSPL; z++) s += g_opart[(size_t)z * B_ * OUT_ + idx];
        out[idx] = s;
    }
}

// ---------------- launch ----------------
extern "C" void kernel_launch(void* const* d_in, const int* in_sizes, int n_in,
                              void* d_out, int out_size)
{
    const int*   node_ids  = (const int*)  d_in[0];
    const float* tim       = (const float*)d_in[3];
    const float* embed     = (const float*)d_in[6];
    const float* kernel_w  = (const float*)d_in[7];
    const float* kernel_b  = (const float*)d_in[8];
    const float* rec_w     = (const float*)d_in[9];
    const float* rec_b     = (const float*)d_in[10];
    const float* scale_w   = (const float*)d_in[11];
    const float* scale_b   = (const float*)d_in[12];
    const float* rescale_w = (const float*)d_in[13];
    const float* rescale_b = (const float*)d_in[14];
    const float* conv_w    = (const float*)d_in[15];
    const float* conv_b    = (const float*)d_in[16];
    const float* out_w     = (const float*)d_in[17];
    const float* out_b     = (const float*)d_in[18];

    float* out   = (float*)d_out;
    float* dists = out + B_ * OUT_;

    const int pre_smem  = 126976;
    const int scan_smem = 228864;
    static int s_attr_done = 0;
    if (!s_attr_done) {
        cudaFuncSetAttribute(k_pre_gemm, cudaFuncAttributeMaxDynamicSharedMemorySize, pre_smem);
        cudaFuncSetAttribute(k_scan, cudaFuncAttributeMaxDynamicSharedMemorySize, scan_smem);
        s_attr_done = 1;
    }

    k_prep<<<512, 256>>>(kernel_w, rec_w, conv_w, embed, kernel_b, rec_b);
    k_pre_gemm<<<dim3(100, 25), 256, pre_smem>>>(node_ids, tim);

    k_scan<<<dim3(24, 4), 256, scan_smem>>>(dists);

    k_mean<<<B_ * V_, 384>>>(dists);
    k_scale_gemm<<<200, 256>>>(scale_w, scale_b);
    k_theme_gemm<<<dim3(200, 6), 256>>>(rescale_w, rescale_b);
    k_conv_big<<<dim3(200, 6), 256>>>(conv_b);

    k_out_gemm<<<dim3(4, 2, NSPL), 256>>>(out_w);
    k_reduce_out<<<128, 256>>>(out_b, out);
}

// round 16
// speedup vs baseline: 1.0512x; 1.0512x over previous
#include <cuda_runtime.h>
#include <cuda_bf16.h>
#include <math.h>
#include <stdint.h>

#define B_   256
#define V_   50
#define D_   128
#define H_   384
#define L_   12
#define CS_  10
#define G_   1560
#define ND_  4096
#define HS_  64
#define OUT_ 128
#define KWP  (ND_ + 1)
#define RWP  (H_ + 1)
#define CK_  (H_ * CS_)   // 3840
#define KP   72           // smem row pitch (conflict-free ldmatrix)
#define NEMB 10001
#define NSPL 20           // out-gemm split-K

// ---------------- device scratch ----------------
__device__ float g_XO2[(size_t)V_ * 24 * B_ * 96];   // [t][gb][row][96]
__device__ float g_c[B_ * H_];
__device__ __nv_bfloat16 g_hh[B_ * H_], g_hl[B_ * H_];
__device__ float g_hsf[(size_t)V_ * B_ * H_];     // [t][b][h]
__device__ float g_ld[B_ * V_ * CS_];             // [r=b*V+t][k]
__device__ float g_mean[(size_t)B_ * V_ * H_];
__device__ float g_relu[B_ * V_ * HS_];
__device__ float g_theme[(size_t)B_ * V_ * H_];
__device__ float g_rnn[(size_t)B_ * V_ * H_];     // [b][t][h]
__device__ float g_opart[NSPL * B_ * OUT_];
// pre-converted split-bf16 weights / embed
__device__ __nv_bfloat16 g_kwh[(size_t)G_ * ND_], g_kwl[(size_t)G_ * ND_];
__device__ __nv_bfloat16 g_rwh[G_ * H_], g_rwl[G_ * H_];
__device__ __nv_bfloat16 g_cwh[H_ * CK_], g_cwl[H_ * CK_];
__device__ __nv_bfloat16 g_emh[NEMB * D_], g_eml[NEMB * D_];
__device__ float g_bias2[G_], g_lin2[G_];

// per-rb software barrier state (4 independent groups of 24 blocks)
__device__ volatile unsigned g_gen[4];
__device__ unsigned g_cnt[4];

// fast transcendentals (~2 ulp, safe vs 1e-3 threshold)
__device__ __forceinline__ float fsig(float x) {
    return __fdividef(1.f, 1.f + __expf(-x));
}
__device__ __forceinline__ float ftanh(float x) {
    float xc = fminf(fmaxf(x, -15.f), 15.f);
    float e = __expf(2.f * xc);
    return __fdividef(e - 1.f, e + 1.f);
}
__device__ __forceinline__ float sigf(float x) { return 1.f / (1.f + expf(-x)); }
__device__ __forceinline__ void bf16_split(float a, __nv_bfloat16& h, __nv_bfloat16& l) {
    h = __float2bfloat16(a);
    l = __float2bfloat16(a - __bfloat162float(h));
}

// ---------------- mma helpers ----------------
__device__ __forceinline__ void ldsm4(uint32_t* r, const void* p) {
    uint32_t a = (uint32_t)__cvta_generic_to_shared(p);
    asm volatile("ldmatrix.sync.aligned.m8n8.x4.shared.b16 {%0,%1,%2,%3},[%4];"
                 : "=r"(r[0]), "=r"(r[1]), "=r"(r[2]), "=r"(r[3]) : "r"(a));
}
__device__ __forceinline__ void mma16816(float* c, const uint32_t* a, const uint32_t* b) {
    asm volatile("mma.sync.aligned.m16n8k16.row.col.f32.bf16.bf16.f32 "
                 "{%0,%1,%2,%3},{%4,%5,%6,%7},{%8,%9},{%0,%1,%2,%3};"
                 : "+f"(c[0]), "+f"(c[1]), "+f"(c[2]), "+f"(c[3])
                 : "r"(a[0]), "r"(a[1]), "r"(a[2]), "r"(a[3]), "r"(b[0]), "r"(b[1]));
}

// ---------------- prep: convert weights/embed, zero state ----------------
__global__ void k_prep(const float* __restrict__ kw, const float* __restrict__ rw,
                       const float* __restrict__ cw, const float* __restrict__ embed,
                       const float* __restrict__ kb, const float* __restrict__ rb_)
{
    int64_t i0 = (int64_t)blockIdx.x * blockDim.x + threadIdx.x;
    int64_t stride = (int64_t)gridDim.x * blockDim.x;
    for (int64_t i = i0; i < (int64_t)G_ * ND_; i += stride) {
        int g = (int)(i >> 12), k = (int)(i & (ND_ - 1));
        __nv_bfloat16 h, l;
        bf16_split(kw[(size_t)g * KWP + k], h, l);
        g_kwh[i] = h; g_kwl[i] = l;
    }
    for (int64_t i = i0; i < (int64_t)G_ * H_; i += stride) {
        int g = (int)(i / H_), k = (int)(i % H_);
        __nv_bfloat16 h, l;
        bf16_split(rw[(size_t)g * RWP + k], h, l);
        g_rwh[i] = h; g_rwl[i] = l;
    }
    for (int64_t i = i0; i < (int64_t)H_ * CK_; i += stride) {
        int o = (int)(i / CK_), rem = (int)(i % CK_);
        int k = rem / H_, hh = rem % H_;
        __nv_bfloat16 h, l;
        bf16_split(cw[((size_t)o * H_ + hh) * CS_ + k], h, l);
        g_cwh[i] = h; g_cwl[i] = l;
    }
    for (int64_t i = i0; i < (int64_t)NEMB * D_; i += stride) {
        __nv_bfloat16 h, l;
        bf16_split(embed[i], h, l);
        g_emh[i] = h; g_eml[i] = l;
    }
    for (int64_t i = i0; i < G_; i += stride) {
        g_bias2[i] = kb[i] + rb_[i];
        g_lin2[i]  = kw[(size_t)i * KWP + ND_] + rw[(size_t)i * RWP + H_];
    }
    __nv_bfloat16 zb = __float2bfloat16(0.f);
    for (int64_t i = i0; i < B_ * H_; i += stride) { g_c[i] = 0.f; g_hh[i] = zb; g_hl[i] = zb; }
}

// ---------------- phase 1: XO2 = gather(embed) @ kernel_w.T + bias2 + tv*lin2 ----
// 128x64 block tile, 8 warps of 32x32 (R13 structure — 3 CTA/SM occupancy).
__global__ void __launch_bounds__(256) k_pre_gemm(
    const int* __restrict__ node_ids, const float* __restrict__ tim)
{
    extern __shared__ char smp[];
    __nv_bfloat16 (*Ah)[KP] = (__nv_bfloat16 (*)[KP])(smp);              // 128x72
    __nv_bfloat16 (*Al)[KP] = (__nv_bfloat16 (*)[KP])(smp + 18432);
    __nv_bfloat16 (*Bh)[KP] = (__nv_bfloat16 (*)[KP])(smp + 36864);      // 64x72
    __nv_bfloat16 (*Bl)[KP] = (__nv_bfloat16 (*)[KP])(smp + 46080);
    int (*ids)[32]          = (int (*)[32])(smp + 55296);                // 128x32

    const int tid = threadIdx.x, lane = tid & 31, wid = tid >> 5;
    const int r0 = blockIdx.x * 128, g0 = blockIdx.y * 64;
    const int m0w = (wid & 3) * 32, n0w = (wid >> 2) * 32;
    float acc[2][4][4];
#pragma unroll
    for (int mt = 0; mt < 2; mt++)
#pragma unroll
        for (int nt = 0; nt < 4; nt++)
#pragma unroll
            for (int e = 0; e < 4; e++) acc[mt][nt][e] = 0.f;

    for (int idx = tid; idx < 128 * 32; idx += 256) {
        int row = idx >> 5, c = idx & 31;
        int r = r0 + row;
        ids[row][c] = node_ids[((r & 255) * V_ + (r >> 8)) * 32 + c];
    }
    __syncthreads();

    const int lrA = tid >> 1, lkA = (tid & 1) * 32;
    const int lrB = tid >> 2, lkB = (tid & 3) * 16;

    for (int k0 = 0; k0 < ND_; k0 += 64) {
        {
            size_t base = (size_t)ids[lrA][k0 >> 7] * D_ + (k0 & 127) + lkA;
#pragma unroll
            for (int q = 0; q < 4; q++) {
                *(uint4*)&Ah[lrA][lkA + q * 8] = *(const uint4*)(g_emh + base + q * 8);
                *(uint4*)&Al[lrA][lkA + q * 8] = *(const uint4*)(g_eml + base + q * 8);
            }
        }
        {
            int g = g0 + lrB;
            if (g < G_) {
                size_t base = (size_t)g * ND_ + k0 + lkB;
                *(uint4*)&Bh[lrB][lkB]     = *(const uint4*)(g_kwh + base);
                *(uint4*)&Bh[lrB][lkB + 8] = *(const uint4*)(g_kwh + base + 8);
                *(uint4*)&Bl[lrB][lkB]     = *(const uint4*)(g_kwl + base);
                *(uint4*)&Bl[lrB][lkB + 8] = *(const uint4*)(g_kwl + base + 8);
            } else {
                uint4 z = {0, 0, 0, 0};
                *(uint4*)&Bh[lrB][lkB] = z; *(uint4*)&Bh[lrB][lkB + 8] = z;
                *(uint4*)&Bl[lrB][lkB] = z; *(uint4*)&Bl[lrB][lkB + 8] = z;
            }
        }
        __syncthreads();
#pragma unroll
        for (int kh = 0; kh < 64; kh += 16) {
            uint32_t ah[2][4], al[2][4], bh[4][2], bl[4][2], t4[4];
            const int ar = lane & 15, ac = kh + (lane >> 4) * 8;
#pragma unroll
            for (int mt = 0; mt < 2; mt++) {
                ldsm4(ah[mt], &Ah[m0w + mt * 16 + ar][ac]);
                ldsm4(al[mt], &Al[m0w + mt * 16 + ar][ac]);
            }
            const int brow = ((lane >> 4) << 3) + (lane & 7);
            const int bcol = kh + ((lane >> 3) & 1) * 8;
#pragma unroll
            for (int p = 0; p < 2; p++) {
                ldsm4(t4, &Bh[n0w + p * 16 + brow][bcol]);
                bh[p * 2][0] = t4[0]; bh[p * 2][1] = t4[1];
                bh[p * 2 + 1][0] = t4[2]; bh[p * 2 + 1][1] = t4[3];
                ldsm4(t4, &Bl[n0w + p * 16 + brow][bcol]);
                bl[p * 2][0] = t4[0]; bl[p * 2][1] = t4[1];
                bl[p * 2 + 1][0] = t4[2]; bl[p * 2 + 1][1] = t4[3];
            }
#pragma unroll
            for (int mt = 0; mt < 2; mt++)
#pragma unroll
                for (int nt = 0; nt < 4; nt++) {
                    mma16816(acc[mt][nt], ah[mt], bh[nt]);
                    mma16816(acc[mt][nt], ah[mt], bl[nt]);
                    mma16816(acc[mt][nt], al[mt], bh[nt]);
                }
        }
        __syncthreads();
    }

    // epilogue: scatter into XO2 [t][gb][row(b)][96]
#pragma unroll
    for (int mt = 0; mt < 2; mt++)
#pragma unroll
        for (int half = 0; half < 2; half++) {
            int row = r0 + m0w + mt * 16 + (lane >> 2) + half * 8;
            int b = row & 255, v = row >> 8;
            float tv = tim[b * V_ + v];
#pragma unroll
            for (int nt = 0; nt < 4; nt++)
#pragma unroll
                for (int e = 0; e < 2; e++) {
                    int g = g0 + n0w + nt * 8 + (lane & 3) * 2 + e;
                    if (g < G_) {
                        float val = acc[mt][nt][half * 2 + e] + g_bias2[g] + tv * g_lin2[g];
                        if (g < 24) {
                            for (int gb2 = 0; gb2 < 24; gb2++)
                                g_XO2[((size_t)(v * 24 + gb2) * B_ + b) * 96 + g] = val;
                        } else {
                            int q = g - 24;
                            int seg = q / 384;
                            int hl = q - seg * 384;
                            int gb = hl >> 4;
                            int j = 24 + seg * 16 + (hl & 15);
                            g_XO2[((size_t)(v * 24 + gb) * B_ + b) * 96 + j] = val;
                        }
                    }
                }
        }
}

// ---------------- fused persistent scan ----------------
// per-rb barrier: only the 24 blocks sharing rb need to sync (they produce/consume
// the same 64 rows of g_hh/g_hl).
__device__ __forceinline__ void gbar_rb(int rb) {
    __syncthreads();
    if (threadIdx.x == 0) {
        unsigned g = g_gen[rb];
        __threadfence();
        if (atomicAdd(&g_cnt[rb], 1u) == 23u) {
            g_cnt[rb] = 0;
            __threadfence();
            g_gen[rb] = g + 1u;
        } else {
            while (g_gen[rb] == g) { }
        }
        __threadfence();
    }
    __syncthreads();
}

__device__ __forceinline__ int scan_gcol(int j, int gb) {
    if (j < 24) return j;
    int q = j - 24, seg = q >> 4, hl = q & 15;
    return 24 + seg * 384 + 16 * gb + hl;
}

// smem: BH 0..82944, BL ..165888, Ah ..175104, Al ..184320,
//       s_xo (64x100 f32) ..209920, fmv ..210176, imv ..210432
__global__ void __launch_bounds__(256) k_scan(float* __restrict__ dists)
{
    extern __shared__ char sm[];
    __nv_bfloat16* BHall = (__nv_bfloat16*)(sm);
    __nv_bfloat16* BLall = (__nv_bfloat16*)(sm + 82944);
    __nv_bfloat16 (*Ah)[KP] = (__nv_bfloat16 (*)[KP])(sm + 165888);
    __nv_bfloat16 (*Al)[KP] = (__nv_bfloat16 (*)[KP])(sm + 175104);
    float (*s_xo)[100]      = (float (*)[100])(sm + 184320);
    float* s_fmv            = (float*)(sm + 209920);
    float* s_imv            = (float*)(sm + 210176);

    const int tid = threadIdx.x, lane = tid & 31, wid = tid >> 5;
    const int gb = blockIdx.x, rb = blockIdx.y;
    const int m0 = (wid & 3) * 16;
    const int n0 = (wid >> 2) * 48;
    const int lfm = gb >> 1;

    // preload resident B: rec_w tile for this gb
    for (int idx = tid; idx < 6 * 96 * 8; idx += 256) {
        int c = idx / 768, rem = idx - c * 768;
        int j = rem >> 3, q = (rem & 7) * 8;
        __nv_bfloat16* dh = BHall + (size_t)(c * 96 + j) * KP + q;
        __nv_bfloat16* dl = BLall + (size_t)(c * 96 + j) * KP + q;
        if (j < 88) {
            int g = scan_gcol(j, gb);
            size_t base = (size_t)g * H_ + c * 64 + q;
            *(uint4*)dh = *(const uint4*)(g_rwh + base);
            *(uint4*)dl = *(const uint4*)(g_rwl + base);
        } else {
            uint4 z = {0, 0, 0, 0};
            *(uint4*)dh = z; *(uint4*)dl = z;
        }
    }
    __syncthreads();

    for (int t = 0; t < V_; t++) {
        float acc[6][4];
#pragma unroll
        for (int nf = 0; nf < 6; nf++)
#pragma unroll
            for (int e = 0; e < 4; e++) acc[nf][e] = 0.f;

        for (int c = 0; c < 6; c++) {
            // load A chunk: h rows
            for (int idx = tid; idx < 64 * 8; idx += 256) {
                int r = idx >> 3, q = (idx & 7) * 8;
                size_t base = (size_t)(rb * 64 + r) * H_ + c * 64 + q;
                *(uint4*)&Ah[r][q] = *(const uint4*)(g_hh + base);
                *(uint4*)&Al[r][q] = *(const uint4*)(g_hl + base);
            }
            __syncthreads();
#pragma unroll
            for (int kh = 0; kh < 64; kh += 16) {
                uint32_t ah[4], al[4], bh[6][2], bl[6][2], t4[4];
                const int ar = lane & 15, ac = kh + (lane >> 4) * 8;
                ldsm4(ah, &Ah[m0 + ar][ac]);
                ldsm4(al, &Al[m0 + ar][ac]);
                const int brow = ((lane >> 4) << 3) + (lane & 7);
                const int bcol = kh + ((lane >> 3) & 1) * 8;
#pragma unroll
                for (int p = 0; p < 3; p++) {
                    const __nv_bfloat16* bp = BHall + (size_t)(c * 96 + n0 + p * 16 + brow) * KP + bcol;
                    ldsm4(t4, bp);
                    bh[p * 2][0] = t4[0]; bh[p * 2][1] = t4[1];
                    bh[p * 2 + 1][0] = t4[2]; bh[p * 2 + 1][1] = t4[3];
                    const __nv_bfloat16* bq = BLall + (size_t)(c * 96 + n0 + p * 16 + brow) * KP + bcol;
                    ldsm4(t4, bq);
                    bl[p * 2][0] = t4[0]; bl[p * 2][1] = t4[1];
                    bl[p * 2 + 1][0] = t4[2]; bl[p * 2 + 1][1] = t4[3];
                }
#pragma unroll
                for (int nf = 0; nf < 6; nf++) {
                    mma16816(acc[nf], ah, bh[nf]);
                    mma16816(acc[nf], ah, bl[nf]);
                    mma16816(acc[nf], al, bh[nf]);
                }
            }
            __syncthreads();
        }

        // epilogue: xo = acc + XO2 (coalesced float2 reads)
        {
            const float* xob = g_XO2 + ((size_t)(t * 24 + gb) * B_ + rb * 64) * 96;
            const int rloc0 = m0 + (lane >> 2);
#pragma unroll
            for (int half = 0; half < 2; half++) {
                int rloc = rloc0 + half * 8;
#pragma unroll
                for (int nf = 0; nf < 6; nf++) {
                    int j = n0 + nf * 8 + (lane & 3) * 2;
                    if (j < 88) {
                        float2 x = *(const float2*)(xob + (size_t)rloc * 96 + j);
                        s_xo[rloc][j]     = acc[nf][half * 2]     + x.x;
                        s_xo[rloc][j + 1] = acc[nf][half * 2 + 1] + x.y;
                    }
                }
            }
        }
        __syncthreads();

        // fm/im (fast exp)
        if (tid < 64) {
            const int r = tid;
            float a[L_], mx = -1e30f;
#pragma unroll
            for (int i = 0; i < L_; i++) { a[i] = s_xo[r][i]; mx = fmaxf(mx, a[i]); }
            float s = 0.f;
#pragma unroll
            for (int i = 0; i < L_; i++) { a[i] = __expf(a[i] - mx); s += a[i]; }
            float inv = __fdividef(1.f, s), cum = 0.f, fsum = 0.f, fmv = 0.f;
#pragma unroll
            for (int i = 0; i < L_; i++) {
                cum += a[i] * inv;
                if (i == lfm) fmv = cum;
                fsum += cum;
            }
            s_fmv[r] = fmv;
            if (gb == 0) dists[t * B_ + rb * 64 + r] = 1.f - fsum / (float)L_;
        } else if (tid < 128) {
            const int r = tid - 64;
            float a[L_], mx = -1e30f;
#pragma unroll
            for (int i = 0; i < L_; i++) { a[i] = s_xo[r][12 + i]; mx = fmaxf(mx, a[i]); }
            float s = 0.f;
#pragma unroll
            for (int i = 0; i < L_; i++) { a[i] = __expf(a[i] - mx); s += a[i]; }
            float suf = 0.f, imv = 0.f;
#pragma unroll
            for (int i = L_ - 1; i >= 0; i--) {
                suf += a[i];
                if (i == lfm) imv = suf;
            }
            s_imv[r] = __fdividef(imv, s);
        }
        __syncthreads();

        // cell/h update: 64 rows x 16 h (fast sigmoid/tanh)
#pragma unroll
        for (int q = tid; q < 1024; q += 256) {
            const int r = q >> 4, hloc = q & 15;
            const int b = rb * 64 + r, h = 16 * gb + hloc;
            float f  = fsig(s_xo[r][24 + hloc]);
            float i_ = fsig(s_xo[r][40 + hloc]);
            float o  = fsig(s_xo[r][56 + hloc]);
            float ci = ftanh(s_xo[r][72 + hloc]);
            float cc = g_c[b * H_ + h];
            float fm = s_fmv[r], im = s_imv[r], ov = fm * im;
            float cn = ov * (f * cc + i_ * ci) + (fm - ov) * cc + (im - ov) * ci;
            float hn = o * ftanh(cn);
            g_c[b * H_ + h] = cn;
            __nv_bfloat16 hh, hl; bf16_split(hn, hh, hl);
            g_hh[b * H_ + h] = hh; g_hl[b * H_ + h] = hl;
            g_hsf[((size_t)t * B_ + b) * H_ + h] = hn;
            g_rnn[((size_t)b * V_ + t) * H_ + h] = hn;
        }

        gbar_rb(rb);
    }
}

// ---------------- post: ld (warp-parallel) + mean over window ----------------
__global__ void __launch_bounds__(384) k_mean(const float* __restrict__ dists)
{
    const int r = blockIdx.x, tid = threadIdx.x;
    const int b = r / V_, t = r - b * V_;
    __shared__ float sld[16];
    if (tid < 32) {
        int lane = tid;
        int j = t - 9 + lane;
        float d = (lane < CS_ && j >= 0) ? dists[j * B_ + b] : 0.f;
        float c = d;
#pragma unroll
        for (int o = 1; o < 16; o <<= 1) {
            float n = __shfl_up_sync(0xFFFFFFFF, c, o);
            if (lane >= o) c += n;
        }
        float mx = (lane < CS_) ? c : -1e30f;
#pragma unroll
        for (int o = 16; o > 0; o >>= 1) mx = fmaxf(mx, __shfl_xor_sync(0xFFFFFFFF, mx, o));
        float e = (lane < CS_) ? __expf(c - mx) : 0.f;
        float s = e;
#pragma unroll
        for (int o = 16; o > 0; o >>= 1) s += __shfl_xor_sync(0xFFFFFFFF, s, o);
        float v = __fdividef(e, s);
        if (lane < CS_) { sld[lane] = v; g_ld[r * CS_ + lane] = v; }
    }
    __syncthreads();
    const int j0 = (t - 9 < 0) ? 0 : t - 9;
    const float* p = g_hsf + ((size_t)j0 * B_ + b) * H_ + tid;
    float m = 0.f;
    for (int j = j0; j <= t; j++) {
        m += (*p) * sld[j - t + 9];
        p += (size_t)B_ * H_;
    }
    g_mean[(size_t)r * H_ + tid] = m * (1.f / (float)CS_);
}

// ---------------- post: relu(mean @ scale_w.T + b) ----------------
__global__ void __launch_bounds__(256) k_scale_gemm(
    const float* __restrict__ sw, const float* __restrict__ sb)
{
    __shared__ float As[32][65];
    __shared__ float Bs[32][65];
    const int tid = threadIdx.x;
    const int r0 = blockIdx.x * 64;
    const int ty = tid >> 4, tx = tid & 15;
    float acc[4][4] = {};
    const int lrb = tid >> 5, lkk = tid & 31;

    for (int k0 = 0; k0 < H_; k0 += 32) {
#pragma unroll
        for (int j = 0; j < 8; j++) {
            int r = lrb + 8 * j;
            As[lkk][r] = g_mean[(size_t)(r0 + r) * H_ + k0 + lkk];
            Bs[lkk][r] = (r < HS_) ? sw[r * H_ + k0 + lkk] : 0.f;
        }
        __syncthreads();
#pragma unroll
        for (int kk = 0; kk < 32; kk++) {
            float ra[4], rb[4];
#pragma unroll
            for (int m = 0; m < 4; m++) ra[m] = As[kk][ty * 4 + m];
#pragma unroll
            for (int n = 0; n < 4; n++) rb[n] = Bs[kk][tx * 4 + n];
#pragma unroll
            for (int m = 0; m < 4; m++)
#pragma unroll
                for (int n = 0; n < 4; n++) acc[m][n] += ra[m] * rb[n];
        }
        __syncthreads();
    }
#pragma unroll
    for (int m = 0; m < 4; m++) {
        int r = r0 + ty * 4 + m;
#pragma unroll
        for (int n = 0; n < 4; n++) {
            int s2 = tx * 4 + n;
            if (s2 < HS_) g_relu[r * HS_ + s2] = fmaxf(acc[m][n] + sb[s2], 0.f);
        }
    }
}

// ---------------- post: theme = sigmoid(relu @ rescale_w.T + b) ----------------
__global__ void __launch_bounds__(256) k_theme_gemm(
    const float* __restrict__ rsw, const float* __restrict__ rsb)
{
    __shared__ float As[32][65];
    __shared__ float Bs[32][65];
    const int tid = threadIdx.x;
    const int r0 = blockIdx.x * 64, o0 = blockIdx.y * 64;
    const int ty = tid >> 4, tx = tid & 15;
    float acc[4][4] = {};
    const int lrb = tid >> 5, lkk = tid & 31;

    for (int k0 = 0; k0 < HS_; k0 += 32) {
#pragma unroll
        for (int j = 0; j < 8; j++) {
            int r = lrb + 8 * j;
            As[lkk][r] = g_relu[(r0 + r) * HS_ + k0 + lkk];
            Bs[lkk][r] = rsw[(o0 + r) * HS_ + k0 + lkk];
        }
        __syncthreads();
#pragma unroll
        for (int kk = 0; kk < 32; kk++) {
            float ra[4], rb[4];
#pragma unroll
            for (int m = 0; m < 4; m++) ra[m] = As[kk][ty * 4 + m];
#pragma unroll
            for (int n = 0; n < 4; n++) rb[n] = Bs[kk][tx * 4 + n];
#pragma unroll
            for (int m = 0; m < 4; m++)
#pragma unroll
                for (int n = 0; n < 4; n++) acc[m][n] += ra[m] * rb[n];
        }
        __syncthreads();
    }
#pragma unroll
    for (int m = 0; m < 4; m++) {
        int r = r0 + ty * 4 + m;
#pragma unroll
        for (int n = 0; n < 4; n++) {
            int o = o0 + tx * 4 + n;
            g_theme[(size_t)r * H_ + o] = sigf(acc[m][n] + rsb[o]);
        }
    }
}

// ---------------- post: conv GEMM over ALL t, lh on the fly ----------------
__global__ void __launch_bounds__(256) k_conv_big(const float* __restrict__ cb)
{
    __shared__ __nv_bfloat16 Ah[64][KP], Al[64][KP], Bh[64][KP], Bl[64][KP];
    const int tid = threadIdx.x, lane = tid & 31, wid = tid >> 5;
    const int r0 = blockIdx.x * 64, o0 = blockIdx.y * 64;
    const int m0w = (wid & 1) * 32, n0w = (wid >> 1) * 16;
    float acc[2][2][4] = {};
    const int lr = tid >> 2, lk = (tid & 3) * 16;
    const int rr = r0 + lr, bb = rr / V_, tt = rr % V_;

    for (int k0 = 0; k0 < CK_; k0 += 64) {
        const int k = k0 / H_;
        const int hb = k0 % H_;
        const int j = tt - (CS_ - 1) + k;
        if (j >= 0) {
            const float ldv = g_ld[rr * CS_ + k];
            const float* hp = g_hsf + ((size_t)j * B_ + bb) * H_ + hb + lk;
#pragma unroll
            for (int q = 0; q < 4; q++) {
                float4 v = *(const float4*)(hp + q * 4);
                float va[4] = {v.x * ldv, v.y * ldv, v.z * ldv, v.w * ldv};
#pragma unroll
                for (int e = 0; e < 4; e++) {
                    __nv_bfloat16 h, l; bf16_split(va[e], h, l);
                    Ah[lr][lk + q * 4 + e] = h; Al[lr][lk + q * 4 + e] = l;
                }
            }
        } else {
            uint4 z = {0, 0, 0, 0};
            *(uint4*)&Ah[lr][lk] = z; *(uint4*)&Ah[lr][lk + 8] = z;
            *(uint4*)&Al[lr][lk] = z; *(uint4*)&Al[lr][lk + 8] = z;
        }
        *(uint4*)&Bh[lr][lk]     = *(const uint4*)(g_cwh + (size_t)(o0 + lr) * CK_ + k0 + lk);
        *(uint4*)&Bh[lr][lk + 8] = *(const uint4*)(g_cwh + (size_t)(o0 + lr) * CK_ + k0 + lk + 8);
        *(uint4*)&Bl[lr][lk]     = *(const uint4*)(g_cwl + (size_t)(o0 + lr) * CK_ + k0 + lk);
        *(uint4*)&Bl[lr][lk + 8] = *(const uint4*)(g_cwl + (size_t)(o0 + lr) * CK_ + k0 + lk + 8);
        __syncthreads();
#pragma unroll
        for (int kh = 0; kh < 64; kh += 16) {
            uint32_t ah[2][4], al[2][4], bh[2][2], bl[2][2], t4[4];
            const int ar = lane & 15, ac = kh + (lane >> 4) * 8;
#pragma unroll
            for (int mt = 0; mt < 2; mt++) {
                ldsm4(ah[mt], &Ah[m0w + mt * 16 + ar][ac]);
                ldsm4(al[mt], &Al[m0w + mt * 16 + ar][ac]);
            }
            const int brow = ((lane >> 4) << 3) + (lane & 7);
            const int bcol = kh + ((lane >> 3) & 1) * 8;
            ldsm4(t4, &Bh[n0w + brow][bcol]);
            bh[0][0] = t4[0]; bh[0][1] = t4[1]; bh[1][0] = t4[2]; bh[1][1] = t4[3];
            ldsm4(t4, &Bl[n0w + brow][bcol]);
            bl[0][0] = t4[0]; bl[0][1] = t4[1]; bl[1][0] = t4[2]; bl[1][1] = t4[3];
#pragma unroll
            for (int mt = 0; mt < 2; mt++)
#pragma unroll
                for (int nt = 0; nt < 2; nt++) {
                    mma16816(acc[mt][nt], ah[mt], bh[nt]);
                    mma16816(acc[mt][nt], ah[mt], bl[nt]);
                    mma16816(acc[mt][nt], al[mt], bh[nt]);
                }
        }
        __syncthreads();
    }

#pragma unroll
    for (int mt = 0; mt < 2; mt++)
#pragma unroll
        for (int half = 0; half < 2; half++) {
            int row = r0 + m0w + mt * 16 + (lane >> 2) + half * 8;
#pragma unroll
            for (int nt = 0; nt < 2; nt++)
#pragma unroll
                for (int e = 0; e < 2; e++) {
                    int o = o0 + n0w + nt * 8 + (lane & 3) * 2 + e;
                    float conv = acc[mt][nt][half * 2 + e] + cb[o];
                    g_rnn[(size_t)row * H_ + o] += g_theme[(size_t)row * H_ + o] * conv;
                }
        }
}

// ---------------- final out GEMM (fp32 SIMT, split-K 20) ----------------
__global__ void __launch_bounds__(256) k_out_gemm(const float* __restrict__ ow)
{
    __shared__ float As[32][65];
    __shared__ float Bs[32][65];
    const int tid = threadIdx.x;
    const int r0 = blockIdx.x * 64, o0 = blockIdx.y * 64;
    const int z = blockIdx.z, kbase = z * 960;
    const int ty = tid >> 4, tx = tid & 15;
    float acc[4][4] = {};
    const int lrb = tid >> 5, lkk = tid & 31;

    for (int k0 = 0; k0 < 960; k0 += 32) {
#pragma unroll
        for (int j = 0; j < 8; j++) {
            int r = lrb + 8 * j;
            As[lkk][r] = g_rnn[(size_t)(r0 + r) * (V_ * H_) + kbase + k0 + lkk];
            Bs[lkk][r] = ow[(size_t)(o0 + r) * (V_ * H_) + kbase + k0 + lkk];
        }
        __syncthreads();
#pragma unroll
        for (int kk = 0; kk < 32; kk++) {
            float ra[4], rb[4];
#pragma unroll
            for (int m = 0; m < 4; m++) ra[m] = As[kk][ty * 4 + m];
#pragma unroll
            for (int n = 0; n < 4; n++) rb[n] = Bs[kk][tx * 4 + n];
#pragma unroll
            for (int m = 0; m < 4; m++)
#pragma unroll
                for (int n = 0; n < 4; n++) acc[m][n] += ra[m] * rb[n];
        }
        __syncthreads();
    }
#pragma unroll
    for (int m = 0; m < 4; m++) {
        int r = r0 + ty * 4 + m;
#pragma unroll
        for (int n = 0; n < 4; n++) {
            int o = o0 + tx * 4 + n;
            g_opart[((size_t)z * B_ + r) * OUT_ + o] = acc[m][n];
        }
    }
}

__global__ void k_reduce_out(const float* __restrict__ ob, float* __restrict__ out)
{
    int idx = blockIdx.x * blockDim.x + threadIdx.x;
    if (idx < B_ * OUT_) {
        float s = ob[idx & (OUT_ - 1)];
#pragma unroll
        for (int z = 0; z < NSPL; z++) s += g_opart[(size_t)z * B_ * OUT_ + idx];
        out[idx] = s;
    }
}

// ---------------- launch ----------------
extern "C" void kernel_launch(void* const* d_in, const int* in_sizes, int n_in,
                              void* d_out, int out_size)
{
    const int*   node_ids  = (const int*)  d_in[0];
    const float* tim       = (const float*)d_in[3];
    const float* embed     = (const float*)d_in[6];
    const float* kernel_w  = (const float*)d_in[7];
    const float* kernel_b  = (const float*)d_in[8];
    const float* rec_w     = (const float*)d_in[9];
    const float* rec_b     = (const float*)d_in[10];
    const float* scale_w   = (const float*)d_in[11];
    const float* scale_b   = (const float*)d_in[12];
    const float* rescale_w = (const float*)d_in[13];
    const float* rescale_b = (const float*)d_in[14];
    const float* conv_w    = (const float*)d_in[15];
    const float* conv_b    = (const float*)d_in[16];
    const float* out_w     = (const float*)d_in[17];
    const float* out_b     = (const float*)d_in[18];

    float* out   = (float*)d_out;
    float* dists = out + B_ * OUT_;

    const int pre_smem  = 71680;
    const int scan_smem = 210432;
    static int s_attr_done = 0;
    if (!s_attr_done) {
        cudaFuncSetAttribute(k_pre_gemm, cudaFuncAttributeMaxDynamicSharedMemorySize, pre_smem);
        cudaFuncSetAttribute(k_scan, cudaFuncAttributeMaxDynamicSharedMemorySize, scan_smem);
        s_attr_done = 1;
    }

    k_prep<<<512, 256>>>(kernel_w, rec_w, conv_w, embed, kernel_b, rec_b);
    k_pre_gemm<<<dim3(100, 25), 256, pre_smem>>>(node_ids, tim);

    k_scan<<<dim3(24, 4), 256, scan_smem>>>(dists);

    k_mean<<<B_ * V_, 384>>>(dists);
    k_scale_gemm<<<200, 256>>>(scale_w, scale_b);
    k_theme_gemm<<<dim3(200, 6), 256>>>(rescale_w, rescale_b);
    k_conv_big<<<dim3(200, 6), 256>>>(conv_b);

    k_out_gemm<<<dim3(4, 2, NSPL), 256>>>(out_w);
    k_reduce_out<<<128, 256>>>(out_b, out);
}